// round 8
// baseline (speedup 1.0000x reference)
#include <cuda_runtime.h>
#include <cuda_bf16.h>

// Analytic reduction of the 4-op "nibble machine":
//   t      = x3*(1 - x10) + x[b, tok=3, col=1]
//   rawsum = x4 + x0 * t
//   result = x5 + (k>=3 ? rawsum[b, k-3] : 0)
// all other 61 columns: identity copy.
//
// Persistent grid-stride streaming kernel: 592 blocks (4/SM, warp-cap
// occupancy) each loop over chunks of 1024 float4s. Within a chunk each
// thread owns 4 float4s at stride 256; chunk bases are multiples of 16, so
// the in-token position (c4) is uniform per thread per chunk and the patch
// branch is evaluated once. 14/16 threads are pure LDG.128x4 -> STG.128x4.

constexpr int THREADS = 256;
constexpr int VEC = 4;                        // float4s per thread per chunk
constexpr int CHUNK4 = THREADS * VEC;         // 1024 float4s per chunk
constexpr int BLOCKS = 148 * 4;               // persistent: 4 blocks/SM

__global__ __launch_bounds__(THREADS)
void nibble_persist_kernel(const float* __restrict__ in, float* __restrict__ out,
                           unsigned nchunks)
{
    const float4* __restrict__ in4 = reinterpret_cast<const float4*>(in);
    float4* __restrict__ out4 = reinterpret_cast<float4*>(out);

    const unsigned c4 = threadIdx.x & 15u;    // uniform across chunks & VEC

    for (unsigned chunk = blockIdx.x; chunk < nchunks; chunk += gridDim.x) {
        const unsigned i0 = chunk * CHUNK4 + threadIdx.x;   // float4 index

        float4 v[VEC];
#pragma unroll
        for (int j = 0; j < VEC; j++)
            v[j] = __ldcs(in4 + i0 + j * THREADS);

        if (c4 <= 1u) {
#pragma unroll
            for (int j = 0; j < VEC; j++) {
                const unsigned i  = i0 + j * THREADS;
                const unsigned tb = (i & ~15u) * 4u;     // token base (floats)
                const unsigned rb = (i & ~127u) * 4u;    // row base   (floats)
                const float b_bc = __ldg(in + rb + 3 * 64 + 1);  // x[b,tok3,col1]

                if (c4 == 0u) {
                    // v = cols {0,1,2,3}; patch col 3 (TEMP)
                    const float x10 = __ldg(in + tb + 10);
                    v[j].w = fmaf(v[j].w, 1.0f - x10, b_bc);
                } else {
                    // v = cols {4,5,6,7}; patch col 4 (RAW_SUM), col 5 (RESULT)
                    const float x0  = __ldg(in + tb + 0);
                    const float x3  = __ldg(in + tb + 3);
                    const float x10 = __ldg(in + tb + 10);
                    const float t   = fmaf(x3, 1.0f - x10, b_bc);
                    v[j].x = fmaf(x0, t, v[j].x);                 // rawsum

                    const unsigned k = (i >> 4) & 7u;             // token index
                    if (k >= 3u) {
                        const float* p = in + tb - 3 * 64;        // token k-3
                        const float tp = fmaf(__ldg(p + 3), 1.0f - __ldg(p + 10), b_bc);
                        v[j].y += fmaf(__ldg(p + 0), tp, __ldg(p + 4)); // + rawsum[k-3]
                    }
                }
            }
        }

#pragma unroll
        for (int j = 0; j < VEC; j++)
            __stcs(out4 + i0 + j * THREADS, v[j]);
    }
}

extern "C" void kernel_launch(void* const* d_in, const int* in_sizes, int n_in,
                              void* d_out, int out_size)
{
    const float* x = (const float*)d_in[0];
    float* out = (float*)d_out;

    int total = in_sizes[0];                  // BATCH * 8 * 64 floats
    if (total <= 0) total = out_size;
    const unsigned nchunks = (unsigned)(total / 4 / CHUNK4);   // 16384

    const unsigned grid = (nchunks < BLOCKS) ? nchunks : BLOCKS;
    nibble_persist_kernel<<<grid, THREADS>>>(x, out, nchunks);
}

// round 9
// speedup vs baseline: 1.5825x; 1.5825x over previous
#include <cuda_runtime.h>
#include <cuda_bf16.h>

// Analytic reduction of the 4-op "nibble machine":
//   t      = x3*(1 - x10) + x[b, tok=3, col=1]
//   rawsum = x4 + x0 * t
//   result = x5 + (k>=3 ? rawsum[b, k-3] : 0)
// all other 61 columns: identity copy.
//
// Final config (best measured across R2..R8 sweep):
//   - flat grid 16384 x 256, VEC=4 block-strided float4s per thread
//     (stride 256 ≡ 0 mod 16 -> in-token position c4 uniform per thread,
//      patch branch evaluated once; 14/16 threads are pure copies, MLP=4)
//   - plain (caching) loads: patch threads re-read a few scalars from
//     sectors the bulk stream just fetched; keeping them L2-resident matters
//     (ldcs evict-first measurably regressed)
//   - __stcs stores: write stream bypasses L2 residency
//   - 32-bit indexing, 32 regs, occ ~84%, DRAM ~80% of spec HBM
// Rejected by measurement: smem staging (L1-bound), VEC=8 (reg pressure,
// occ 43%), persistent grid-stride (serialized chunks, DRAM 59%).

constexpr int THREADS = 256;
constexpr int VEC = 4;                        // float4s per thread
constexpr int BLK4 = THREADS * VEC;           // 1024 float4s per block

__global__ __launch_bounds__(THREADS)
void nibble_final_kernel(const float* __restrict__ in, float* __restrict__ out)
{
    const unsigned i0 = blockIdx.x * BLK4 + threadIdx.x;   // float4 index

    const float4* __restrict__ in4 = reinterpret_cast<const float4*>(in);
    float4* __restrict__ out4 = reinterpret_cast<float4*>(out);

    float4 v[VEC];
#pragma unroll
    for (int j = 0; j < VEC; j++)
        v[j] = in4[i0 + j * THREADS];

    const unsigned c4 = i0 & 15u;             // same for all VEC elements

    if (c4 <= 1u) {
#pragma unroll
        for (int j = 0; j < VEC; j++) {
            const unsigned i  = i0 + j * THREADS;
            const unsigned tb = (i & ~15u) * 4u;     // token base (floats)
            const unsigned rb = (i & ~127u) * 4u;    // row base   (floats)
            const float b_bc = __ldg(in + rb + 3 * 64 + 1);  // x[b,tok3,col1]

            if (c4 == 0u) {
                // v = cols {0,1,2,3}; patch col 3 (TEMP)
                const float x10 = __ldg(in + tb + 10);
                v[j].w = fmaf(v[j].w, 1.0f - x10, b_bc);
            } else {
                // v = cols {4,5,6,7}; patch col 4 (RAW_SUM), col 5 (RESULT)
                const float x0  = __ldg(in + tb + 0);
                const float x3  = __ldg(in + tb + 3);
                const float x10 = __ldg(in + tb + 10);
                const float t   = fmaf(x3, 1.0f - x10, b_bc);
                v[j].x = fmaf(x0, t, v[j].x);                 // rawsum

                const unsigned k = (i >> 4) & 7u;             // token index
                if (k >= 3u) {
                    const float* p = in + tb - 3 * 64;        // token k-3
                    const float tp = fmaf(__ldg(p + 3), 1.0f - __ldg(p + 10), b_bc);
                    v[j].y += fmaf(__ldg(p + 0), tp, __ldg(p + 4)); // + rawsum[k-3]
                }
            }
        }
    }

#pragma unroll
    for (int j = 0; j < VEC; j++)
        __stcs(out4 + i0 + j * THREADS, v[j]);
}

extern "C" void kernel_launch(void* const* d_in, const int* in_sizes, int n_in,
                              void* d_out, int out_size)
{
    const float* x = (const float*)d_in[0];
    float* out = (float*)d_out;

    int total = in_sizes[0];                  // BATCH * 8 * 64 floats
    if (total <= 0) total = out_size;
    const int total4 = total / 4;             // float4 count (16,777,216)
    const int blocks = total4 / BLK4;         // 16384
    nibble_final_kernel<<<blocks, THREADS>>>(x, out);
}